// round 1
// baseline (speedup 1.0000x reference)
#include <cuda_runtime.h>
#include <cuda_bf16.h>
#include <math.h>

#define Bsz 512
#define Tt  512
#define Ee  32
#define H1C 128
#define G1  512
#define H2C 64
#define G2  256
#define VV  32000
#define RWS 4

static __device__ float g_h1[(size_t)Bsz * Tt * H1C];  // LSTM1 output (BN applied)
static __device__ float g_h2[Bsz * H2C];               // LSTM2 last-step output (BN applied)

__device__ __forceinline__ float sigf(float x) {
    float ev = __expf(-x);
    return __fdividef(1.0f, 1.0f + ev);
}

// ---------------------------------------------------------------------------
// Kernel 1: LSTM1 (relu activation) + BN1. 128 CTAs x 4 batch rows, 512 thr.
// Thread j owns output column j of the 4H1=512 gate pre-activations.
// U1 rows 0..95 in smem, rows 96..127 in regs; W1 column in regs.
// ---------------------------------------------------------------------------
#define SMEM1_FLOATS (96*G1 + 2*Ee*RWS + RWS*G1 + H1C*RWS + RWS*Tt)
#define SMEM1_BYTES  (SMEM1_FLOATS * 4)

__global__ void __launch_bounds__(512, 1) lstm1_kernel(
    const int*   __restrict__ ids, const float* __restrict__ emb,
    const float* __restrict__ w1,  const float* __restrict__ u1,
    const float* __restrict__ b1,  const float* __restrict__ g1,
    const float* __restrict__ be1, const float* __restrict__ m1,
    const float* __restrict__ v1)
{
    extern __shared__ float sm[];
    float* sU   = sm;                         // 96*512
    float* sXT  = sU  + 96*G1;                // 2 * 32*4  (x transposed [e][r])
    float* sZ   = sXT + 2*Ee*RWS;             // 4*512
    float* sHf  = sZ  + RWS*G1;               // 128*4     (h transposed [m][r])
    int*   sIds = (int*)(sHf + H1C*RWS);      // 4*512

    const int j  = threadIdx.x;
    const int r0 = blockIdx.x * RWS;

    float rW[Ee];
    #pragma unroll
    for (int e = 0; e < Ee; e++) rW[e] = w1[e*G1 + j];
    float rU[32];
    #pragma unroll
    for (int k = 0; k < 32; k++) rU[k] = u1[(96+k)*G1 + j];
    const float b1j = b1[j];

    for (int k = 0; k < 96; k++) sU[k*G1 + j] = u1[k*G1 + j];

    for (int i = j; i < RWS*Tt; i += 512) {
        int r = i >> 9, tt = i & (Tt-1);
        sIds[r*Tt + tt] = ids[(r0 + r)*Tt + tt];
    }

    // combiner role: (row rr, hidden m)
    const int rr = j >> 7, m = j & 127;
    const float bnsc = g1[m] / sqrtf(v1[m] + 1e-3f);
    const float bnsh = be1[m] - bnsc * m1[m];
    float creg = 0.f;

    sHf[j] = 0.f;
    __syncthreads();

    if (j < 128) {
        int r = j >> 5, e = j & 31;
        sXT[e*RWS + r] = emb[(size_t)sIds[r*Tt + 0]*Ee + e];
    }
    __syncthreads();

    for (int t = 0; t < Tt; t++) {
        const int cur = t & 1;
        float xpf = 0.f;
        const bool pf = (t + 1 < Tt) && (j < 128);
        const int pr = j >> 5, pe = j & 31;
        if (pf) xpf = emb[(size_t)sIds[pr*Tt + t + 1]*Ee + pe];

        float a0 = b1j, a1 = b1j, a2 = b1j, a3 = b1j;
        const float4* x4p = (const float4*)(sXT + cur*Ee*RWS);
        #pragma unroll
        for (int e = 0; e < Ee; e++) {
            float4 x4 = x4p[e];
            a0 = fmaf(rW[e], x4.x, a0);
            a1 = fmaf(rW[e], x4.y, a1);
            a2 = fmaf(rW[e], x4.z, a2);
            a3 = fmaf(rW[e], x4.w, a3);
        }
        const float4* h4p = (const float4*)sHf;
        #pragma unroll 8
        for (int k = 0; k < 96; k++) {
            float  u  = sU[k*G1 + j];
            float4 h4 = h4p[k];
            a0 = fmaf(u, h4.x, a0);
            a1 = fmaf(u, h4.y, a1);
            a2 = fmaf(u, h4.z, a2);
            a3 = fmaf(u, h4.w, a3);
        }
        #pragma unroll 8
        for (int k = 0; k < 32; k++) {
            float  u  = rU[k];
            float4 h4 = h4p[96 + k];
            a0 = fmaf(u, h4.x, a0);
            a1 = fmaf(u, h4.y, a1);
            a2 = fmaf(u, h4.z, a2);
            a3 = fmaf(u, h4.w, a3);
        }
        sZ[0*G1 + j] = a0;
        sZ[1*G1 + j] = a1;
        sZ[2*G1 + j] = a2;
        sZ[3*G1 + j] = a3;
        if (pf) sXT[(cur^1)*Ee*RWS + pe*RWS + pr] = xpf;
        __syncthreads();

        // gate combine: i,f,g,o at m, m+128, m+256, m+384
        float zi = sZ[rr*G1 + m];
        float zf = sZ[rr*G1 + m + 128];
        float zg = sZ[rr*G1 + m + 256];
        float zo = sZ[rr*G1 + m + 384];
        float ig = sigf(zi), fg = sigf(zf), og = sigf(zo);
        float gg = fmaxf(zg, 0.f);
        creg = fmaf(fg, creg, ig * gg);
        float h = og * fmaxf(creg, 0.f);
        sHf[m*RWS + rr] = h;
        g_h1[((size_t)(r0 + rr)*Tt + t)*H1C + m] = fmaf(h, bnsc, bnsh);
        __syncthreads();
    }
}

// ---------------------------------------------------------------------------
// Kernel 2: LSTM2 + BN2 (last step only). 128 CTAs x 4 rows, 256 threads.
// W2 (128x256) and U2 (64x256) both in smem (192 KB).
// ---------------------------------------------------------------------------
#define SMEM2_FLOATS (H1C*G2 + H2C*G2 + 2*H1C*RWS + RWS*G2 + H2C*RWS)
#define SMEM2_BYTES  (SMEM2_FLOATS * 4)

__global__ void __launch_bounds__(256, 1) lstm2_kernel(
    const float* __restrict__ w2,  const float* __restrict__ u2,
    const float* __restrict__ b2,  const float* __restrict__ g2,
    const float* __restrict__ be2, const float* __restrict__ m2,
    const float* __restrict__ v2)
{
    extern __shared__ float sm[];
    float* sW  = sm;                          // 128*256
    float* sUU = sW  + H1C*G2;                // 64*256
    float* sXT = sUU + H2C*G2;                // 2 * 128*4
    float* sZ  = sXT + 2*H1C*RWS;             // 4*256
    float* sHf = sZ  + RWS*G2;                // 64*4

    const int j  = threadIdx.x;
    const int r0 = blockIdx.x * RWS;

    for (int i = j; i < H1C*G2; i += 256) sW[i]  = w2[i];
    for (int i = j; i < H2C*G2; i += 256) sUU[i] = u2[i];
    const float b2j = b2[j];

    const int rr = j >> 6, m = j & 63;
    const float bnsc = g2[m] / sqrtf(v2[m] + 1e-3f);
    const float bnsh = be2[m] - bnsc * m2[m];
    float creg = 0.f;

    sHf[j & 255] = 0.f;  // 256 floats
    __syncthreads();

    const int ra = j >> 7, ma = j & 127;
    const int rb = 2 + (j >> 7), mb = j & 127;
    sXT[ma*RWS + ra] = g_h1[((size_t)(r0 + ra)*Tt + 0)*H1C + ma];
    sXT[mb*RWS + rb] = g_h1[((size_t)(r0 + rb)*Tt + 0)*H1C + mb];
    __syncthreads();

    for (int t = 0; t < Tt; t++) {
        const int cur = t & 1;
        float xpf0 = 0.f, xpf1 = 0.f;
        const bool pf = (t + 1 < Tt);
        if (pf) {
            xpf0 = g_h1[((size_t)(r0 + ra)*Tt + t + 1)*H1C + ma];
            xpf1 = g_h1[((size_t)(r0 + rb)*Tt + t + 1)*H1C + mb];
        }
        float a0 = b2j, a1 = b2j, a2 = b2j, a3 = b2j;
        const float4* x4p = (const float4*)(sXT + cur*H1C*RWS);
        #pragma unroll 8
        for (int k = 0; k < H1C; k++) {
            float  w  = sW[k*G2 + j];
            float4 x4 = x4p[k];
            a0 = fmaf(w, x4.x, a0);
            a1 = fmaf(w, x4.y, a1);
            a2 = fmaf(w, x4.z, a2);
            a3 = fmaf(w, x4.w, a3);
        }
        const float4* h4p = (const float4*)sHf;
        #pragma unroll 8
        for (int k = 0; k < H2C; k++) {
            float  u  = sUU[k*G2 + j];
            float4 h4 = h4p[k];
            a0 = fmaf(u, h4.x, a0);
            a1 = fmaf(u, h4.y, a1);
            a2 = fmaf(u, h4.z, a2);
            a3 = fmaf(u, h4.w, a3);
        }
        sZ[0*G2 + j] = a0;
        sZ[1*G2 + j] = a1;
        sZ[2*G2 + j] = a2;
        sZ[3*G2 + j] = a3;
        if (pf) {
            sXT[(cur^1)*H1C*RWS + ma*RWS + ra] = xpf0;
            sXT[(cur^1)*H1C*RWS + mb*RWS + rb] = xpf1;
        }
        __syncthreads();

        float zi = sZ[rr*G2 + m];
        float zf = sZ[rr*G2 + m + 64];
        float zg = sZ[rr*G2 + m + 128];
        float zo = sZ[rr*G2 + m + 192];
        float ig = sigf(zi), fg = sigf(zf), og = sigf(zo);
        float gg = fmaxf(zg, 0.f);
        creg = fmaf(fg, creg, ig * gg);
        float h = og * fmaxf(creg, 0.f);
        sHf[m*RWS + rr] = h;
        if (t == Tt - 1)
            g_h2[(r0 + rr)*H2C + m] = fmaf(h, bnsc, bnsh);
        __syncthreads();
    }
}

// ---------------------------------------------------------------------------
// Kernel 3a: logits + exp. 125 CTAs x 256 vocab columns; each thread owns one
// wd column (64 regs), loops over all 512 batch rows; h2 broadcast from smem.
// ---------------------------------------------------------------------------
#define SMEM3_BYTES (Bsz * H2C * 4)

__global__ void __launch_bounds__(256, 1) head_kernel(
    const float* __restrict__ wd, const float* __restrict__ bd,
    float* __restrict__ out)
{
    extern __shared__ float sH2s[];  // 512*64
    const int j = threadIdx.x;
    const int v = blockIdx.x * 256 + j;

    for (int i = j; i < Bsz*H2C; i += 256) sH2s[i] = g_h2[i];

    float rwd[H2C];
    #pragma unroll
    for (int k = 0; k < H2C; k++) rwd[k] = wd[(size_t)k*VV + v];
    const float bdv = bd[v];
    __syncthreads();

    for (int r = 0; r < Bsz; r += 4) {
        float a0 = bdv, a1 = bdv, a2 = bdv, a3 = bdv;
        const float* h0 = &sH2s[(r + 0)*H2C];
        const float* h1 = &sH2s[(r + 1)*H2C];
        const float* h2 = &sH2s[(r + 2)*H2C];
        const float* h3 = &sH2s[(r + 3)*H2C];
        #pragma unroll 16
        for (int k = 0; k < H2C; k++) {
            float w = rwd[k];
            a0 = fmaf(h0[k], w, a0);
            a1 = fmaf(h1[k], w, a1);
            a2 = fmaf(h2[k], w, a2);
            a3 = fmaf(h3[k], w, a3);
        }
        out[(size_t)(r + 0)*VV + v] = __expf(a0);
        out[(size_t)(r + 1)*VV + v] = __expf(a1);
        out[(size_t)(r + 2)*VV + v] = __expf(a2);
        out[(size_t)(r + 3)*VV + v] = __expf(a3);
    }
}

// ---------------------------------------------------------------------------
// Kernel 3b: per-row normalize. 512 CTAs (one per batch row).
// Logits are O(1) post-BN, so exp() without max-shift is safe in fp32.
// ---------------------------------------------------------------------------
__global__ void __launch_bounds__(256, 1) softmax_norm_kernel(float* __restrict__ out)
{
    __shared__ float warp_s[8];
    __shared__ float inv_s;
    const int r = blockIdx.x;
    float4* p = (float4*)(out + (size_t)r * VV);

    float s = 0.f;
    for (int i = threadIdx.x; i < VV/4; i += 256) {
        float4 v = p[i];
        s += (v.x + v.y) + (v.z + v.w);
    }
    #pragma unroll
    for (int o = 16; o > 0; o >>= 1) s += __shfl_down_sync(0xffffffffu, s, o);
    if ((threadIdx.x & 31) == 0) warp_s[threadIdx.x >> 5] = s;
    __syncthreads();
    if (threadIdx.x == 0) {
        float tt = 0.f;
        #pragma unroll
        for (int i = 0; i < 8; i++) tt += warp_s[i];
        inv_s = 1.0f / tt;
    }
    __syncthreads();
    const float inv = inv_s;
    for (int i = threadIdx.x; i < VV/4; i += 256) {
        float4 v = p[i];
        v.x *= inv; v.y *= inv; v.z *= inv; v.w *= inv;
        p[i] = v;
    }
}

// ---------------------------------------------------------------------------
extern "C" void kernel_launch(void* const* d_in, const int* in_sizes, int n_in,
                              void* d_out, int out_size)
{
    const int*   ids = (const int*)  d_in[0];
    const float* emb = (const float*)d_in[1];
    const float* w1  = (const float*)d_in[2];
    const float* u1  = (const float*)d_in[3];
    const float* b1  = (const float*)d_in[4];
    const float* g1  = (const float*)d_in[5];
    const float* be1 = (const float*)d_in[6];
    const float* m1  = (const float*)d_in[7];
    const float* v1  = (const float*)d_in[8];
    const float* w2  = (const float*)d_in[9];
    const float* u2  = (const float*)d_in[10];
    const float* b2  = (const float*)d_in[11];
    const float* g2  = (const float*)d_in[12];
    const float* be2 = (const float*)d_in[13];
    const float* m2  = (const float*)d_in[14];
    const float* v2  = (const float*)d_in[15];
    const float* wd  = (const float*)d_in[16];
    const float* bd  = (const float*)d_in[17];
    float* out = (float*)d_out;

    cudaFuncSetAttribute(lstm1_kernel, cudaFuncAttributeMaxDynamicSharedMemorySize, SMEM1_BYTES);
    cudaFuncSetAttribute(lstm2_kernel, cudaFuncAttributeMaxDynamicSharedMemorySize, SMEM2_BYTES);
    cudaFuncSetAttribute(head_kernel,  cudaFuncAttributeMaxDynamicSharedMemorySize, SMEM3_BYTES);

    lstm1_kernel<<<Bsz/RWS, 512, SMEM1_BYTES>>>(ids, emb, w1, u1, b1, g1, be1, m1, v1);
    lstm2_kernel<<<Bsz/RWS, 256, SMEM2_BYTES>>>(w2, u2, b2, g2, be2, m2, v2);
    head_kernel<<<VV/256, 256, SMEM3_BYTES>>>(wd, bd, out);
    softmax_norm_kernel<<<Bsz, 256>>>(out);
}

// round 2
// speedup vs baseline: 1.0109x; 1.0109x over previous
#include <cuda_runtime.h>
#include <cuda_bf16.h>
#include <math.h>

#define Bsz 512
#define Tt  512
#define Ee  32
#define H1C 128
#define G1  512
#define H2C 64
#define G2  256
#define VV  32000
#define RWS 4

typedef unsigned long long ull;

static __device__ float g_h1[(size_t)Bsz * Tt * H1C];  // LSTM1 output (BN applied)
static __device__ float g_h2[Bsz * H2C];               // LSTM2 last-step output (BN applied)

__device__ __forceinline__ float sigf(float x) {
    float ev = __expf(-x);
    return __fdividef(1.0f, 1.0f + ev);
}

__device__ __forceinline__ ull pack2(float a, float b) {
    ull r;
    asm("mov.b64 %0, {%1,%2};" : "=l"(r) : "f"(a), "f"(b));
    return r;
}
__device__ __forceinline__ ull dup2(float a) { return pack2(a, a); }

__device__ __forceinline__ void ffma2(ull& d, ull a, ull b) {
    asm("fma.rn.f32x2 %0, %1, %2, %0;" : "+l"(d) : "l"(a), "l"(b));
}
__device__ __forceinline__ float2 unpk2(ull v) {
    float2 r;
    asm("mov.b64 {%0,%1}, %2;" : "=f"(r.x), "=f"(r.y) : "l"(v));
    return r;
}

// ---------------------------------------------------------------------------
// Kernel 1: LSTM1 (relu) + BN1. 128 CTAs x 4 batch rows, 512 threads.
// Thread j owns gate column j of 4H1=512. 4 rows packed as 2x f32x2.
// U1 rows 0..95 in smem, rows 96..127 in regs; W1 column in regs.
// ---------------------------------------------------------------------------
#define SMEM1_FLOATS (96*G1 + 2*Ee*RWS + RWS*G1 + H1C*RWS + RWS*Tt)
#define SMEM1_BYTES  (SMEM1_FLOATS * 4)

__global__ void __launch_bounds__(512, 1) lstm1_kernel(
    const int*   __restrict__ ids, const float* __restrict__ emb,
    const float* __restrict__ w1,  const float* __restrict__ u1,
    const float* __restrict__ b1,  const float* __restrict__ g1,
    const float* __restrict__ be1, const float* __restrict__ m1,
    const float* __restrict__ v1)
{
    extern __shared__ float sm[];
    float* sU   = sm;                         // 96*512
    float* sXT  = sU  + 96*G1;                // 2 * 32*4  x transposed [e][r]
    float* sZ   = sXT + 2*Ee*RWS;             // 2*512 ull (row-pairs x cols)
    float* sHf  = sZ  + RWS*G1;               // 128*4     h transposed [m][r]
    int*   sIds = (int*)(sHf + H1C*RWS);      // 4*512

    const int j  = threadIdx.x;
    const int r0 = blockIdx.x * RWS;

    float rW[Ee];
    #pragma unroll
    for (int e = 0; e < Ee; e++) rW[e] = w1[e*G1 + j];
    float rU[32];
    #pragma unroll
    for (int k = 0; k < 32; k++) rU[k] = u1[(96+k)*G1 + j];
    const ull bb = dup2(b1[j]);

    for (int k = 0; k < 96; k++) sU[k*G1 + j] = u1[k*G1 + j];

    for (int i = j; i < RWS*Tt; i += 512) {
        int r = i >> 9, tt = i & (Tt-1);
        sIds[r*Tt + tt] = ids[(r0 + r)*Tt + tt];
    }

    // combiner role: (row rr, hidden m)
    const int rr = j >> 7, m = j & 127;
    const float bnsc = g1[m] / sqrtf(v1[m] + 1e-3f);
    const float bnsh = be1[m] - bnsc * m1[m];
    float creg = 0.f;

    sHf[j] = 0.f;
    __syncthreads();

    if (j < 128) {
        int r = j >> 5, e = j & 31;
        sXT[e*RWS + r] = emb[(size_t)sIds[r*Tt + 0]*Ee + e];
    }
    __syncthreads();

    for (int t = 0; t < Tt; t++) {
        const int cur = t & 1;
        float xpf = 0.f;
        const bool pf = (t + 1 < Tt) && (j < 128);
        const int pr = j >> 5, pe = j & 31;
        if (pf) xpf = emb[(size_t)sIds[pr*Tt + t + 1]*Ee + pe];

        ull a01 = bb, a23 = bb;
        const ulonglong2* x2p = (const ulonglong2*)(sXT + cur*Ee*RWS);
        #pragma unroll
        for (int e = 0; e < Ee; e++) {
            ull w2 = dup2(rW[e]);
            ulonglong2 xv = x2p[e];
            ffma2(a01, w2, xv.x);
            ffma2(a23, w2, xv.y);
        }
        const ulonglong2* h2p = (const ulonglong2*)sHf;
        #pragma unroll 8
        for (int k = 0; k < 96; k++) {
            ull u2 = dup2(sU[k*G1 + j]);
            ulonglong2 hv = h2p[k];
            ffma2(a01, u2, hv.x);
            ffma2(a23, u2, hv.y);
        }
        #pragma unroll 8
        for (int k = 0; k < 32; k++) {
            ull u2 = dup2(rU[k]);
            ulonglong2 hv = h2p[96 + k];
            ffma2(a01, u2, hv.x);
            ffma2(a23, u2, hv.y);
        }
        ull* sZ64 = (ull*)sZ;
        sZ64[0*G1 + j] = a01;   // rows 0,1
        sZ64[1*G1 + j] = a23;   // rows 2,3
        if (pf) sXT[(cur^1)*Ee*RWS + pe*RWS + pr] = xpf;
        __syncthreads();

        // gate combine: cols m, m+128, m+256, m+384 for row rr
        const int p = rr >> 1, lane = rr & 1;
        const float* sZf = sZ;
        float zi = sZf[(p*G1 + m      )*2 + lane];
        float zf = sZf[(p*G1 + m + 128)*2 + lane];
        float zg = sZf[(p*G1 + m + 256)*2 + lane];
        float zo = sZf[(p*G1 + m + 384)*2 + lane];
        float ig = sigf(zi), fg = sigf(zf), og = sigf(zo);
        float gg = fmaxf(zg, 0.f);
        creg = fmaf(fg, creg, ig * gg);
        float h = og * fmaxf(creg, 0.f);
        sHf[m*RWS + rr] = h;
        g_h1[((size_t)(r0 + rr)*Tt + t)*H1C + m] = fmaf(h, bnsc, bnsh);
        __syncthreads();
    }
}

// ---------------------------------------------------------------------------
// Kernel 2: LSTM2 + BN2 (last step). 128 CTAs x 4 rows, 256 threads.
// ---------------------------------------------------------------------------
#define SMEM2_FLOATS (H1C*G2 + H2C*G2 + 2*H1C*RWS + RWS*G2 + H2C*RWS)
#define SMEM2_BYTES  (SMEM2_FLOATS * 4)

__global__ void __launch_bounds__(256, 1) lstm2_kernel(
    const float* __restrict__ w2,  const float* __restrict__ u2,
    const float* __restrict__ b2,  const float* __restrict__ g2,
    const float* __restrict__ be2, const float* __restrict__ m2,
    const float* __restrict__ v2)
{
    extern __shared__ float sm[];
    float* sW  = sm;                          // 128*256
    float* sUU = sW  + H1C*G2;                // 64*256
    float* sXT = sUU + H2C*G2;                // 2 * 128*4
    float* sZ  = sXT + 2*H1C*RWS;             // 2*256 ull
    float* sHf = sZ  + RWS*G2;                // 64*4

    const int j  = threadIdx.x;
    const int r0 = blockIdx.x * RWS;

    for (int i = j; i < H1C*G2; i += 256) sW[i]  = w2[i];
    for (int i = j; i < H2C*G2; i += 256) sUU[i] = u2[i];
    const ull bb = dup2(b2[j]);

    const int rr = j >> 6, m = j & 63;
    const float bnsc = g2[m] / sqrtf(v2[m] + 1e-3f);
    const float bnsh = be2[m] - bnsc * m2[m];
    float creg = 0.f;

    sHf[j] = 0.f;
    __syncthreads();

    const int ra = j >> 7, ma = j & 127;
    const int rb = 2 + (j >> 7), mb = j & 127;
    sXT[ma*RWS + ra] = g_h1[((size_t)(r0 + ra)*Tt + 0)*H1C + ma];
    sXT[mb*RWS + rb] = g_h1[((size_t)(r0 + rb)*Tt + 0)*H1C + mb];
    __syncthreads();

    for (int t = 0; t < Tt; t++) {
        const int cur = t & 1;
        float xpf0 = 0.f, xpf1 = 0.f;
        const bool pf = (t + 1 < Tt);
        if (pf) {
            xpf0 = g_h1[((size_t)(r0 + ra)*Tt + t + 1)*H1C + ma];
            xpf1 = g_h1[((size_t)(r0 + rb)*Tt + t + 1)*H1C + mb];
        }
        ull a01 = bb, a23 = bb;
        const ulonglong2* x2p = (const ulonglong2*)(sXT + cur*H1C*RWS);
        #pragma unroll 8
        for (int k = 0; k < H1C; k++) {
            ull w2r = dup2(sW[k*G2 + j]);
            ulonglong2 xv = x2p[k];
            ffma2(a01, w2r, xv.x);
            ffma2(a23, w2r, xv.y);
        }
        const ulonglong2* h2p = (const ulonglong2*)sHf;
        #pragma unroll 8
        for (int k = 0; k < H2C; k++) {
            ull u2r = dup2(sUU[k*G2 + j]);
            ulonglong2 hv = h2p[k];
            ffma2(a01, u2r, hv.x);
            ffma2(a23, u2r, hv.y);
        }
        ull* sZ64 = (ull*)sZ;
        sZ64[0*G2 + j] = a01;
        sZ64[1*G2 + j] = a23;
        if (pf) {
            sXT[(cur^1)*H1C*RWS + ma*RWS + ra] = xpf0;
            sXT[(cur^1)*H1C*RWS + mb*RWS + rb] = xpf1;
        }
        __syncthreads();

        const int p = rr >> 1, lane = rr & 1;
        const float* sZf = sZ;
        float zi = sZf[(p*G2 + m      )*2 + lane];
        float zf = sZf[(p*G2 + m +  64)*2 + lane];
        float zg = sZf[(p*G2 + m + 128)*2 + lane];
        float zo = sZf[(p*G2 + m + 192)*2 + lane];
        float ig = sigf(zi), fg = sigf(zf), og = sigf(zo);
        float gg = fmaxf(zg, 0.f);
        creg = fmaf(fg, creg, ig * gg);
        float h = og * fmaxf(creg, 0.f);
        sHf[m*RWS + rr] = h;
        if (t == Tt - 1)
            g_h2[(r0 + rr)*H2C + m] = fmaf(h, bnsc, bnsh);
        __syncthreads();
    }
}

// ---------------------------------------------------------------------------
// Kernel 3a: logits + exp. 125 CTAs x 256 vocab columns; wd column pre-packed
// in 128 regs (f32x2); h2 transposed in smem (stride 514) so row pairs load
// as natural 64-bit packs (broadcast across the warp).
// ---------------------------------------------------------------------------
#define H2T_STRIDE 514
#define SMEM3_BYTES (H2C * H2T_STRIDE * 4)

__global__ void __launch_bounds__(256, 1) head_kernel(
    const float* __restrict__ wd, const float* __restrict__ bd,
    float* __restrict__ out)
{
    extern __shared__ float sH2t[];  // [64][514] transposed h2
    const int j = threadIdx.x;
    const int v = blockIdx.x * 256 + j;

    for (int i = j; i < Bsz*H2C; i += 256) {
        int r = i >> 6, k = i & 63;
        sH2t[k*H2T_STRIDE + r] = g_h2[i];
    }

    ull rwd2[H2C];
    #pragma unroll
    for (int k = 0; k < H2C; k++) rwd2[k] = dup2(wd[(size_t)k*VV + v]);
    const ull bb = dup2(bd[v]);
    __syncthreads();

    for (int r = 0; r < Bsz; r += 4) {
        ull a01 = bb, a23 = bb;
        #pragma unroll 16
        for (int k = 0; k < H2C; k++) {
            const float* hp = sH2t + k*H2T_STRIDE + r;
            ull h01 = *(const ull*)(hp);
            ull h23 = *(const ull*)(hp + 2);
            ffma2(a01, rwd2[k], h01);
            ffma2(a23, rwd2[k], h23);
        }
        float2 f01 = unpk2(a01), f23 = unpk2(a23);
        out[(size_t)(r + 0)*VV + v] = __expf(f01.x);
        out[(size_t)(r + 1)*VV + v] = __expf(f01.y);
        out[(size_t)(r + 2)*VV + v] = __expf(f23.x);
        out[(size_t)(r + 3)*VV + v] = __expf(f23.y);
    }
}

// ---------------------------------------------------------------------------
// Kernel 3b: per-row normalize. 512 CTAs (one per batch row).
// ---------------------------------------------------------------------------
__global__ void __launch_bounds__(256, 1) softmax_norm_kernel(float* __restrict__ out)
{
    __shared__ float warp_s[8];
    __shared__ float inv_s;
    const int r = blockIdx.x;
    float4* p = (float4*)(out + (size_t)r * VV);

    float s = 0.f;
    for (int i = threadIdx.x; i < VV/4; i += 256) {
        float4 v = p[i];
        s += (v.x + v.y) + (v.z + v.w);
    }
    #pragma unroll
    for (int o = 16; o > 0; o >>= 1) s += __shfl_down_sync(0xffffffffu, s, o);
    if ((threadIdx.x & 31) == 0) warp_s[threadIdx.x >> 5] = s;
    __syncthreads();
    if (threadIdx.x == 0) {
        float tt = 0.f;
        #pragma unroll
        for (int i = 0; i < 8; i++) tt += warp_s[i];
        inv_s = 1.0f / tt;
    }
    __syncthreads();
    const float inv = inv_s;
    for (int i = threadIdx.x; i < VV/4; i += 256) {
        float4 v = p[i];
        v.x *= inv; v.y *= inv; v.z *= inv; v.w *= inv;
        p[i] = v;
    }
}

// ---------------------------------------------------------------------------
extern "C" void kernel_launch(void* const* d_in, const int* in_sizes, int n_in,
                              void* d_out, int out_size)
{
    const int*   ids = (const int*)  d_in[0];
    const float* emb = (const float*)d_in[1];
    const float* w1  = (const float*)d_in[2];
    const float* u1  = (const float*)d_in[3];
    const float* b1  = (const float*)d_in[4];
    const float* g1  = (const float*)d_in[5];
    const float* be1 = (const float*)d_in[6];
    const float* m1  = (const float*)d_in[7];
    const float* v1  = (const float*)d_in[8];
    const float* w2  = (const float*)d_in[9];
    const float* u2  = (const float*)d_in[10];
    const float* b2  = (const float*)d_in[11];
    const float* g2  = (const float*)d_in[12];
    const float* be2 = (const float*)d_in[13];
    const float* m2  = (const float*)d_in[14];
    const float* v2  = (const float*)d_in[15];
    const float* wd  = (const float*)d_in[16];
    const float* bd  = (const float*)d_in[17];
    float* out = (float*)d_out;

    cudaFuncSetAttribute(lstm1_kernel, cudaFuncAttributeMaxDynamicSharedMemorySize, SMEM1_BYTES);
    cudaFuncSetAttribute(lstm2_kernel, cudaFuncAttributeMaxDynamicSharedMemorySize, SMEM2_BYTES);
    cudaFuncSetAttribute(head_kernel,  cudaFuncAttributeMaxDynamicSharedMemorySize, SMEM3_BYTES);

    lstm1_kernel<<<Bsz/RWS, 512, SMEM1_BYTES>>>(ids, emb, w1, u1, b1, g1, be1, m1, v1);
    lstm2_kernel<<<Bsz/RWS, 256, SMEM2_BYTES>>>(w2, u2, b2, g2, be2, m2, v2);
    head_kernel<<<VV/256, 256, SMEM3_BYTES>>>(wd, bd, out);
    softmax_norm_kernel<<<Bsz, 256>>>(out);
}

// round 3
// speedup vs baseline: 1.1732x; 1.1606x over previous
#include <cuda_runtime.h>
#include <cuda_bf16.h>
#include <math.h>

#define Bsz 512
#define Tt  512
#define Ee  32
#define H1C 128
#define G1  512
#define H2C 64
#define G2  256
#define VV  32000
#define RWS 4

typedef unsigned long long ull;

static __device__ float g_h1[(size_t)Bsz * Tt * H1C];  // LSTM1 output (BN applied)
static __device__ float g_h2[Bsz * H2C];               // LSTM2 last-step output (BN applied)

__device__ __forceinline__ float sigf(float x) {
    float ev = __expf(-x);
    return __fdividef(1.0f, 1.0f + ev);
}
__device__ __forceinline__ ull pack2(float a, float b) {
    ull r;
    asm("mov.b64 %0, {%1,%2};" : "=l"(r) : "f"(a), "f"(b));
    return r;
}
__device__ __forceinline__ void ffma2(ull& d, ull a, ull b) {
    asm("fma.rn.f32x2 %0, %1, %2, %0;" : "+l"(d) : "l"(a), "l"(b));
}
__device__ __forceinline__ float2 unpk2(ull v) {
    float2 r;
    asm("mov.b64 {%0,%1}, %2;" : "=f"(r.x), "=f"(r.y) : "l"(v));
    return r;
}

// ---------------------------------------------------------------------------
// Kernel 1: LSTM1 (relu) + BN1. 128 CTAs x 4 batch rows, 512 threads.
// Combined input vector v[160] = [x(32); h(128)], processed as 80 k-pairs.
// Pairs 0..31 weights in regs (64 regs), pairs 32..79 in smem as ull.
// v stored pair-interleaved [pair][row][2] so LDS.128 = k-pair x 2 rows.
// ---------------------------------------------------------------------------
#define SMEM1_BYTES (48*G1*8 + 512*16 + 640*4 + RWS*Tt*4)   // 215552

__global__ void __launch_bounds__(512, 1) lstm1_kernel(
    const int*   __restrict__ ids, const float* __restrict__ emb,
    const float* __restrict__ w1,  const float* __restrict__ u1,
    const float* __restrict__ b1,  const float* __restrict__ g1,
    const float* __restrict__ be1, const float* __restrict__ m1,
    const float* __restrict__ v1)
{
    extern __shared__ char smraw[];
    ull*    sUp  = (ull*)smraw;                 // [48][512] weight pairs
    float4* sZ4  = (float4*)(sUp + 48*G1);      // [512] z for 4 rows
    float*  sV   = (float*)(sZ4 + 512);         // [80][4][2] v pair-interleaved
    int*    sIds = (int*)(sV + 640);            // [4][512]

    const int j  = threadIdx.x;
    const int r0 = blockIdx.x * RWS;

    // register weight pairs: v-rows 0..63 (x rows 0..31 -> w1, h rows 0..31 -> u1)
    ull rWU[32];
    #pragma unroll
    for (int i = 0; i < 16; i++)
        rWU[i] = pack2(w1[(2*i)*G1 + j], w1[(2*i+1)*G1 + j]);
    #pragma unroll
    for (int i = 16; i < 32; i++)
        rWU[i] = pack2(u1[(2*i-32)*G1 + j], u1[(2*i-31)*G1 + j]);
    // smem weight pairs: v-rows 64..159 = u1 rows 32..127
    for (int i = 0; i < 48; i++)
        sUp[i*G1 + j] = pack2(u1[(32+2*i)*G1 + j], u1[(33+2*i)*G1 + j]);

    const float b1j = b1[j];

    for (int i = j; i < RWS*Tt; i += 512) {
        int r = i >> 9, tt = i & (Tt-1);
        sIds[r*Tt + tt] = ids[(r0 + r)*Tt + tt];
    }

    // combiner role: (row rr, hidden m)
    const int rr = j >> 7, m = j & 127;
    const float bnsc = g1[m] / sqrtf(v1[m] + 1e-3f);
    const float bnsh = be1[m] - bnsc * m1[m];
    float creg = 0.f;

    // zero v buffer
    for (int i = j; i < 640; i += 512) sV[i] = 0.f;
    __syncthreads();

    // t=0 x
    const int pr = j >> 5, pe = j & 31;
    if (j < 128)
        sV[(pe>>1)*8 + pr*2 + (pe&1)] = emb[(size_t)sIds[pr*Tt + 0]*Ee + pe];
    __syncthreads();

    for (int t = 0; t < Tt; t++) {
        float xpf = 0.f;
        const bool pf = (t + 1 < Tt) && (j < 128);
        if (pf) xpf = emb[(size_t)sIds[pr*Tt + t + 1]*Ee + pe];

        ull a0 = pack2(b1j, 0.f);
        ull a1 = a0, a2 = a0, a3 = a0;

        const ulonglong2* hv2 = (const ulonglong2*)sV;
        #pragma unroll
        for (int i = 0; i < 32; i++) {
            ulonglong2 hA = hv2[i*2];      // (pair,row0),(pair,row1)
            ulonglong2 hB = hv2[i*2 + 1];  // rows 2,3
            ffma2(a0, rWU[i], hA.x);
            ffma2(a1, rWU[i], hA.y);
            ffma2(a2, rWU[i], hB.x);
            ffma2(a3, rWU[i], hB.y);
        }
        #pragma unroll 8
        for (int i = 0; i < 48; i++) {
            ull u2 = sUp[i*G1 + j];
            ulonglong2 hA = hv2[(32+i)*2];
            ulonglong2 hB = hv2[(32+i)*2 + 1];
            ffma2(a0, u2, hA.x);
            ffma2(a1, u2, hA.y);
            ffma2(a2, u2, hB.x);
            ffma2(a3, u2, hB.y);
        }
        float2 f0 = unpk2(a0), f1 = unpk2(a1), f2 = unpk2(a2), f3 = unpk2(a3);
        sZ4[j] = make_float4(f0.x + f0.y, f1.x + f1.y, f2.x + f2.y, f3.x + f3.y);
        __syncthreads();

        // combine: gates i,f,g,o at columns m, m+128, m+256, m+384 ; row rr
        const float* zf = (const float*)sZ4;
        float zi = zf[(m      )*4 + rr];
        float zfv= zf[(m + 128)*4 + rr];
        float zg = zf[(m + 256)*4 + rr];
        float zo = zf[(m + 384)*4 + rr];
        float ig = sigf(zi), fg = sigf(zfv), og = sigf(zo);
        float gg = fmaxf(zg, 0.f);
        creg = fmaf(fg, creg, ig * gg);
        float h = og * fmaxf(creg, 0.f);
        // h row (32+m) -> pair 16 + m/2, slot m&1
        sV[(16 + (m>>1))*8 + rr*2 + (m&1)] = h;
        if (pf) sV[(pe>>1)*8 + pr*2 + (pe&1)] = xpf;
        g_h1[((size_t)(r0 + rr)*Tt + t)*H1C + m] = fmaf(h, bnsc, bnsh);
        __syncthreads();
    }
}

// ---------------------------------------------------------------------------
// Kernel 2: LSTM2 + BN2 (last step). 128 CTAs x 4 rows, 512 threads.
// v[192] = [x=h1(128); h(64)], 96 pairs, split: half 0 = pairs 0..47,
// half 1 = pairs 48..95. Per half: 32 pairs in regs, 16 in smem.
// Partial z from both halves reduced in the combine phase.
// ---------------------------------------------------------------------------
#define SMEM2_BYTES (32*G2*8 + 512*16 + 768*4)   // 76544

__global__ void __launch_bounds__(512, 1) lstm2_kernel(
    const float* __restrict__ w2,  const float* __restrict__ u2,
    const float* __restrict__ b2,  const float* __restrict__ g2,
    const float* __restrict__ be2, const float* __restrict__ m2,
    const float* __restrict__ v2)
{
    extern __shared__ char smraw[];
    ull*    sWp = (ull*)smraw;               // [2][16][256] weight pairs
    float4* sZp = (float4*)(sWp + 32*G2);    // [2][256] partial z
    float*  sV  = (float*)(sZp + 512);       // [96][4][2]

    const int j    = threadIdx.x;
    const int jc   = j & 255;
    const int half = j >> 8;
    const int r0   = blockIdx.x * RWS;

    // weight(rho, c): rho<128 -> w2, else u2
    // reg pairs p=0..31: v-rows 96*half + 2p
    ull rW[32];
    #pragma unroll
    for (int p = 0; p < 32; p++) {
        int rho = 96*half + 2*p;
        float wa = (rho   < 128) ? w2[rho*G2 + jc]     : u2[(rho-128)*G2 + jc];
        float wb = (rho+1 < 128) ? w2[(rho+1)*G2 + jc] : u2[(rho-127)*G2 + jc];
        rW[p] = pack2(wa, wb);
    }
    // smem pairs p=0..15: v-rows 96*half + 64 + 2p
    for (int p = 0; p < 16; p++) {
        int rho = 96*half + 64 + 2*p;
        float wa = (rho   < 128) ? w2[rho*G2 + jc]     : u2[(rho-128)*G2 + jc];
        float wb = (rho+1 < 128) ? w2[(rho+1)*G2 + jc] : u2[(rho-127)*G2 + jc];
        sWp[(half*16 + p)*G2 + jc] = pack2(wa, wb);
    }
    const float bj = b2[jc];

    // combine role (j<256): row rr, hidden m
    const int rr = (j & 255) >> 6, m = j & 63;
    const float bnsc = g2[m] / sqrtf(v2[m] + 1e-3f);
    const float bnsh = be2[m] - bnsc * m2[m];
    float creg = 0.f;

    // v loader role: all 512 threads: batch row vr, h1 row vm
    const int vr = j >> 7, vm = j & 127;

    for (int i = j; i < 768; i += 512) sV[i] = 0.f;
    __syncthreads();

    sV[(vm>>1)*8 + vr*2 + (vm&1)] = g_h1[((size_t)(r0 + vr)*Tt + 0)*H1C + vm];
    __syncthreads();

    for (int t = 0; t < Tt; t++) {
        float xpf = 0.f;
        const bool pf = (t + 1 < Tt);
        if (pf) xpf = g_h1[((size_t)(r0 + vr)*Tt + t + 1)*H1C + vm];

        ull a0 = (half == 0) ? pack2(bj, 0.f) : pack2(0.f, 0.f);
        ull a1 = a0, a2 = a0, a3 = a0;

        const ulonglong2* hv2 = (const ulonglong2*)sV;
        const int gbase = 48 * half;
        #pragma unroll
        for (int p = 0; p < 32; p++) {
            ulonglong2 hA = hv2[(gbase + p)*2];
            ulonglong2 hB = hv2[(gbase + p)*2 + 1];
            ffma2(a0, rW[p], hA.x);
            ffma2(a1, rW[p], hA.y);
            ffma2(a2, rW[p], hB.x);
            ffma2(a3, rW[p], hB.y);
        }
        #pragma unroll 8
        for (int p = 0; p < 16; p++) {
            ull u2r = sWp[(half*16 + p)*G2 + jc];
            ulonglong2 hA = hv2[(gbase + 32 + p)*2];
            ulonglong2 hB = hv2[(gbase + 32 + p)*2 + 1];
            ffma2(a0, u2r, hA.x);
            ffma2(a1, u2r, hA.y);
            ffma2(a2, u2r, hB.x);
            ffma2(a3, u2r, hB.y);
        }
        float2 f0 = unpk2(a0), f1 = unpk2(a1), f2 = unpk2(a2), f3 = unpk2(a3);
        sZp[half*G2 + jc] = make_float4(f0.x + f0.y, f1.x + f1.y, f2.x + f2.y, f3.x + f3.y);
        __syncthreads();

        if (j < 256) {
            const float* zf = (const float*)sZp;
            float zi = zf[(m      )*4 + rr] + zf[(256 + m      )*4 + rr];
            float zfv= zf[(m +  64)*4 + rr] + zf[(256 + m +  64)*4 + rr];
            float zg = zf[(m + 128)*4 + rr] + zf[(256 + m + 128)*4 + rr];
            float zo = zf[(m + 192)*4 + rr] + zf[(256 + m + 192)*4 + rr];
            float ig = sigf(zi), fg = sigf(zfv), og = sigf(zo);
            float gg = fmaxf(zg, 0.f);
            creg = fmaf(fg, creg, ig * gg);
            float h = og * fmaxf(creg, 0.f);
            // h row (128+m) -> pair 64 + m/2
            sV[(64 + (m>>1))*8 + rr*2 + (m&1)] = h;
            if (t == Tt - 1)
                g_h2[(r0 + rr)*H2C + m] = fmaf(h, bnsc, bnsh);
        }
        if (pf) sV[(vm>>1)*8 + vr*2 + (vm&1)] = xpf;
        __syncthreads();
    }
}

// ---------------------------------------------------------------------------
// Kernel 3a: logits + exp. 125 CTAs x 256 vocab columns.
// ---------------------------------------------------------------------------
#define H2T_STRIDE 514
#define SMEM3_BYTES (H2C * H2T_STRIDE * 4)

__global__ void __launch_bounds__(256, 1) head_kernel(
    const float* __restrict__ wd, const float* __restrict__ bd,
    float* __restrict__ out)
{
    extern __shared__ float sH2t[];  // [64][514] transposed h2
    const int j = threadIdx.x;
    const int v = blockIdx.x * 256 + j;

    for (int i = j; i < Bsz*H2C; i += 256) {
        int r = i >> 6, k = i & 63;
        sH2t[k*H2T_STRIDE + r] = g_h2[i];
    }

    ull rwd2[H2C];
    #pragma unroll
    for (int k = 0; k < H2C; k++) {
        float w = wd[(size_t)k*VV + v];
        rwd2[k] = pack2(w, w);
    }
    const float bdv = bd[v];
    const ull bb = pack2(bdv, bdv);
    __syncthreads();

    for (int r = 0; r < Bsz; r += 4) {
        ull a01 = bb, a23 = bb;
        #pragma unroll 16
        for (int k = 0; k < H2C; k++) {
            const float* hp = sH2t + k*H2T_STRIDE + r;
            ull h01 = *(const ull*)(hp);
            ull h23 = *(const ull*)(hp + 2);
            ffma2(a01, rwd2[k], h01);
            ffma2(a23, rwd2[k], h23);
        }
        float2 f01 = unpk2(a01), f23 = unpk2(a23);
        out[(size_t)(r + 0)*VV + v] = __expf(f01.x);
        out[(size_t)(r + 1)*VV + v] = __expf(f01.y);
        out[(size_t)(r + 2)*VV + v] = __expf(f23.x);
        out[(size_t)(r + 3)*VV + v] = __expf(f23.y);
    }
}

// ---------------------------------------------------------------------------
// Kernel 3b: per-row normalize.
// ---------------------------------------------------------------------------
__global__ void __launch_bounds__(256, 1) softmax_norm_kernel(float* __restrict__ out)
{
    __shared__ float warp_s[8];
    __shared__ float inv_s;
    const int r = blockIdx.x;
    float4* p = (float4*)(out + (size_t)r * VV);

    float s = 0.f;
    for (int i = threadIdx.x; i < VV/4; i += 256) {
        float4 v = p[i];
        s += (v.x + v.y) + (v.z + v.w);
    }
    #pragma unroll
    for (int o = 16; o > 0; o >>= 1) s += __shfl_down_sync(0xffffffffu, s, o);
    if ((threadIdx.x & 31) == 0) warp_s[threadIdx.x >> 5] = s;
    __syncthreads();
    if (threadIdx.x == 0) {
        float tt = 0.f;
        #pragma unroll
        for (int i = 0; i < 8; i++) tt += warp_s[i];
        inv_s = 1.0f / tt;
    }
    __syncthreads();
    const float inv = inv_s;
    for (int i = threadIdx.x; i < VV/4; i += 256) {
        float4 v = p[i];
        v.x *= inv; v.y *= inv; v.z *= inv; v.w *= inv;
        p[i] = v;
    }
}

// ---------------------------------------------------------------------------
extern "C" void kernel_launch(void* const* d_in, const int* in_sizes, int n_in,
                              void* d_out, int out_size)
{
    const int*   ids = (const int*)  d_in[0];
    const float* emb = (const float*)d_in[1];
    const float* w1  = (const float*)d_in[2];
    const float* u1  = (const float*)d_in[3];
    const float* b1  = (const float*)d_in[4];
    const float* g1  = (const float*)d_in[5];
    const float* be1 = (const float*)d_in[6];
    const float* m1  = (const float*)d_in[7];
    const float* v1  = (const float*)d_in[8];
    const float* w2  = (const float*)d_in[9];
    const float* u2  = (const float*)d_in[10];
    const float* b2  = (const float*)d_in[11];
    const float* g2  = (const float*)d_in[12];
    const float* be2 = (const float*)d_in[13];
    const float* m2  = (const float*)d_in[14];
    const float* v2  = (const float*)d_in[15];
    const float* wd  = (const float*)d_in[16];
    const float* bd  = (const float*)d_in[17];
    float* out = (float*)d_out;

    cudaFuncSetAttribute(lstm1_kernel, cudaFuncAttributeMaxDynamicSharedMemorySize, SMEM1_BYTES);
    cudaFuncSetAttribute(lstm2_kernel, cudaFuncAttributeMaxDynamicSharedMemorySize, SMEM2_BYTES);
    cudaFuncSetAttribute(head_kernel,  cudaFuncAttributeMaxDynamicSharedMemorySize, SMEM3_BYTES);

    lstm1_kernel<<<Bsz/RWS, 512, SMEM1_BYTES>>>(ids, emb, w1, u1, b1, g1, be1, m1, v1);
    lstm2_kernel<<<Bsz/RWS, 512, SMEM2_BYTES>>>(w2, u2, b2, g2, be2, m2, v2);
    head_kernel<<<VV/256, 256, SMEM3_BYTES>>>(wd, bd, out);
    softmax_norm_kernel<<<Bsz, 256>>>(out);
}

// round 8
// speedup vs baseline: 1.2244x; 1.0436x over previous
#include <cuda_runtime.h>
#include <cuda_bf16.h>
#include <math.h>
#include <stdint.h>

#define Bsz 512
#define Tt  512
#define Ee  32
#define H1C 128
#define G1  512
#define H2C 64
#define G2  256
#define VV  32000
#define RWS 4
#define NR  (Bsz * Tt)          // 262144 combined (b,t) rows

typedef unsigned long long ull;

static __device__ float g_zx1[(size_t)NR * G1];   // x  @ W1   [R][512]
static __device__ float g_zx2[(size_t)NR * G2];   // h1 @ W2   [R][256]
static __device__ float g_h1[(size_t)NR * H1C];   // LSTM1 out (BN applied) [R][128]
static __device__ float g_h2[Bsz * H2C];

// ---------------------------------------------------------------------------
// helpers
// ---------------------------------------------------------------------------
__device__ __forceinline__ float sigf(float x) {
    float ev = __expf(-x);
    return __fdividef(1.0f, 1.0f + ev);
}
__device__ __forceinline__ ull pack2(float a, float b) {
    ull r; asm("mov.b64 %0, {%1,%2};" : "=l"(r) : "f"(a), "f"(b)); return r;
}
__device__ __forceinline__ void ffma2(ull& d, ull a, ull b) {
    asm("fma.rn.f32x2 %0, %1, %2, %0;" : "+l"(d) : "l"(a), "l"(b));
}
__device__ __forceinline__ float2 unpk2(ull v) {
    float2 r; asm("mov.b64 {%0,%1}, %2;" : "=f"(r.x), "=f"(r.y) : "l"(v)); return r;
}

// classic tensor-core mma (sm_80+, works on plain sm_100 target)
__device__ __forceinline__ void mma_bf16(float4& c, const uint32_t* a, const uint32_t* b) {
    asm volatile("mma.sync.aligned.m16n8k16.row.col.f32.bf16.bf16.f32 "
        "{%0,%1,%2,%3}, {%4,%5,%6,%7}, {%8,%9}, {%0,%1,%2,%3};"
        : "+f"(c.x), "+f"(c.y), "+f"(c.z), "+f"(c.w)
        : "r"(a[0]), "r"(a[1]), "r"(a[2]), "r"(a[3]), "r"(b[0]), "r"(b[1]));
}
__device__ __forceinline__ void split_bf16(float x, __nv_bfloat16& h, __nv_bfloat16& l) {
    h = __float2bfloat16(x);
    l = __float2bfloat16(x - __bfloat162float(h));
}

// ---------------------------------------------------------------------------
// zx1 = gather(emb, ids) @ W1  — bf16x3 mma.sync. CTA: 128 rows x 512 cols.
// smem tiles padded to stride 34 (conflict-free b32 LDS).
// ---------------------------------------------------------------------------
#define PK1 34
#define ZX1_SMEM ((128*PK1*2 + 512*PK1*2) * 2)   // aH,aL,bH,bL bf16

__global__ void __launch_bounds__(256, 1) zx1_gemm(
    const int* __restrict__ ids, const float* __restrict__ emb,
    const float* __restrict__ w1)
{
    extern __shared__ __nv_bfloat16 smb[];
    __nv_bfloat16* aH = smb;                 // [128][34]
    __nv_bfloat16* aL = aH + 128*PK1;
    __nv_bfloat16* bH = aL + 128*PK1;        // [512][34]
    __nv_bfloat16* bL = bH + 512*PK1;

    const int tid = threadIdx.x, wid = tid >> 5, lane = tid & 31;
    const size_t R0 = (size_t)blockIdx.x * 128;

    // B[g][k] = w1[k][g]
    for (int idx = tid; idx < Ee * G1; idx += 256) {
        int k = idx >> 9, g = idx & 511;
        split_bf16(w1[idx], bH[g*PK1 + k], bL[g*PK1 + k]);
    }
    // A[row][k] = emb[ids[R0+row]][k]
    {
        int row = tid >> 1;
        int id = ids[R0 + row];
        int base = (tid & 1) * 16;
        const float* er = emb + (size_t)id * Ee + base;
        #pragma unroll
        for (int q = 0; q < 16; q++)
            split_bf16(er[q], aH[row*PK1 + base + q], aL[row*PK1 + base + q]);
    }
    __syncthreads();

    const int rbase = wid * 16;
    const int tr = lane >> 2;          // 0..7
    const int tk = (lane & 3) * 2;     // 0,2,4,6

    // A fragments (2 k-tiles), persist across all n-tiles
    uint32_t ah[2][4], al[2][4];
    #pragma unroll
    for (int kt = 0; kt < 2; kt++) {
        int k0 = kt*16 + tk;
        ah[kt][0] = *(const uint32_t*)&aH[(rbase + tr    )*PK1 + k0];
        ah[kt][1] = *(const uint32_t*)&aH[(rbase + tr + 8)*PK1 + k0];
        ah[kt][2] = *(const uint32_t*)&aH[(rbase + tr    )*PK1 + k0 + 8];
        ah[kt][3] = *(const uint32_t*)&aH[(rbase + tr + 8)*PK1 + k0 + 8];
        al[kt][0] = *(const uint32_t*)&aL[(rbase + tr    )*PK1 + k0];
        al[kt][1] = *(const uint32_t*)&aL[(rbase + tr + 8)*PK1 + k0];
        al[kt][2] = *(const uint32_t*)&aL[(rbase + tr    )*PK1 + k0 + 8];
        al[kt][3] = *(const uint32_t*)&aL[(rbase + tr + 8)*PK1 + k0 + 8];
    }

    float* op = g_zx1 + R0 * G1;
    #pragma unroll 4
    for (int nt = 0; nt < 64; nt++) {
        int nb = nt * 8;
        uint32_t bh[2][2], bl[2][2];
        #pragma unroll
        for (int kt = 0; kt < 2; kt++) {
            int k0 = kt*16 + tk;
            bh[kt][0] = *(const uint32_t*)&bH[(nb + tr)*PK1 + k0];
            bh[kt][1] = *(const uint32_t*)&bH[(nb + tr)*PK1 + k0 + 8];
            bl[kt][0] = *(const uint32_t*)&bL[(nb + tr)*PK1 + k0];
            bl[kt][1] = *(const uint32_t*)&bL[(nb + tr)*PK1 + k0 + 8];
        }
        float4 acc = make_float4(0.f, 0.f, 0.f, 0.f);
        #pragma unroll
        for (int kt = 0; kt < 2; kt++) {
            mma_bf16(acc, ah[kt], bh[kt]);
            mma_bf16(acc, ah[kt], bl[kt]);
            mma_bf16(acc, al[kt], bh[kt]);
        }
        // C frag: rows rbase+tr, rbase+tr+8; cols nb+tk, nb+tk+1
        *(float2*)&op[(size_t)(rbase + tr    )*G1 + nb + tk] = make_float2(acc.x, acc.y);
        *(float2*)&op[(size_t)(rbase + tr + 8)*G1 + nb + tk] = make_float2(acc.z, acc.w);
    }
}

// ---------------------------------------------------------------------------
// zx2 = g_h1 @ W2 — bf16x3 mma.sync. CTA: 128 rows x 128 cols (grid.y = 2).
// ---------------------------------------------------------------------------
#define PK2 132
#define ZX2_SMEM ((128*PK2*2 + 128*PK2*2) * 2)

__global__ void __launch_bounds__(256, 1) zx2_gemm(const float* __restrict__ w2)
{
    extern __shared__ __nv_bfloat16 smb[];
    __nv_bfloat16* aH = smb;                 // [128][132]
    __nv_bfloat16* aL = aH + 128*PK2;
    __nv_bfloat16* bH = aL + 128*PK2;        // [128][132]
    __nv_bfloat16* bL = bH + 128*PK2;

    const int tid = threadIdx.x, wid = tid >> 5, lane = tid & 31;
    const size_t R0 = (size_t)blockIdx.x * 128;
    const int gb = blockIdx.y * 128;

    // B[gl][k] = w2[k][gb+gl]
    for (int idx = tid; idx < 128 * H1C; idx += 256) {
        int k = idx >> 7, gl = idx & 127;
        split_bf16(w2[k*G2 + gb + gl], bH[gl*PK2 + k], bL[gl*PK2 + k]);
    }
    // A[row][k] = g_h1[R0+row][k]
    for (int idx = tid; idx < 128 * H1C; idx += 256)
        split_bf16(g_h1[R0*H1C + idx], aH[(idx >> 7)*PK2 + (idx & 127)],
                   aL[(idx >> 7)*PK2 + (idx & 127)]);
    __syncthreads();

    const int rbase = wid * 16;
    const int tr = lane >> 2;
    const int tk = (lane & 3) * 2;

    uint32_t ah[8][4], al[8][4];
    #pragma unroll
    for (int kt = 0; kt < 8; kt++) {
        int k0 = kt*16 + tk;
        ah[kt][0] = *(const uint32_t*)&aH[(rbase + tr    )*PK2 + k0];
        ah[kt][1] = *(const uint32_t*)&aH[(rbase + tr + 8)*PK2 + k0];
        ah[kt][2] = *(const uint32_t*)&aH[(rbase + tr    )*PK2 + k0 + 8];
        ah[kt][3] = *(const uint32_t*)&aH[(rbase + tr + 8)*PK2 + k0 + 8];
        al[kt][0] = *(const uint32_t*)&aL[(rbase + tr    )*PK2 + k0];
        al[kt][1] = *(const uint32_t*)&aL[(rbase + tr + 8)*PK2 + k0];
        al[kt][2] = *(const uint32_t*)&aL[(rbase + tr    )*PK2 + k0 + 8];
        al[kt][3] = *(const uint32_t*)&aL[(rbase + tr + 8)*PK2 + k0 + 8];
    }

    float* op = g_zx2 + R0 * G2 + gb;
    #pragma unroll 2
    for (int nt = 0; nt < 16; nt++) {
        int nb = nt * 8;
        float4 acc = make_float4(0.f, 0.f, 0.f, 0.f);
        #pragma unroll
        for (int kt = 0; kt < 8; kt++) {
            int k0 = kt*16 + tk;
            uint32_t bh[2], bl[2];
            bh[0] = *(const uint32_t*)&bH[(nb + tr)*PK2 + k0];
            bh[1] = *(const uint32_t*)&bH[(nb + tr)*PK2 + k0 + 8];
            bl[0] = *(const uint32_t*)&bL[(nb + tr)*PK2 + k0];
            bl[1] = *(const uint32_t*)&bL[(nb + tr)*PK2 + k0 + 8];
            mma_bf16(acc, ah[kt], bh);
            mma_bf16(acc, ah[kt], bl);
            mma_bf16(acc, al[kt], bh);
        }
        *(float2*)&op[(size_t)(rbase + tr    )*G2 + nb + tk] = make_float2(acc.x, acc.y);
        *(float2*)&op[(size_t)(rbase + tr + 8)*G2 + nb + tk] = make_float2(acc.z, acc.w);
    }
}

// ---------------------------------------------------------------------------
// Kernel: LSTM1 recurrence only (k=128) + BN1. 128 CTAs x 4 rows, 512 thr.
// sV = 64 k-pairs x 4 rows x 2 = 512 floats  (R7 bug: was sized 256)
// ---------------------------------------------------------------------------
#define SMEM1_BYTES (48*G1*8 + 512*16 + 512*4)

__global__ void __launch_bounds__(512, 1) lstm1_kernel(
    const float* __restrict__ u1, const float* __restrict__ b1,
    const float* __restrict__ g1, const float* __restrict__ be1,
    const float* __restrict__ m1, const float* __restrict__ v1)
{
    extern __shared__ char smraw[];
    ull*    sUp = (ull*)smraw;               // [48][512] u1 rows 32..127 pairs
    float4* sZ4 = (float4*)(sUp + 48*G1);    // [512]
    float*  sV  = (float*)(sZ4 + 512);       // [64 pairs][4][2] = 512 floats

    const int j  = threadIdx.x;
    const int r0 = blockIdx.x * RWS;
    const float* zx = g_zx1;

    ull rU[16];
    #pragma unroll
    for (int i = 0; i < 16; i++)
        rU[i] = pack2(u1[(2*i)*G1 + j], u1[(2*i+1)*G1 + j]);
    for (int i = 0; i < 48; i++)
        sUp[i*G1 + j] = pack2(u1[(32+2*i)*G1 + j], u1[(33+2*i)*G1 + j]);
    const float b1j = b1[j];

    const int rr = j >> 7, m = j & 127;
    const float bnsc = g1[m] / sqrtf(v1[m] + 1e-3f);
    const float bnsh = be1[m] - bnsc * m1[m];
    float creg = 0.f;

    sV[j] = 0.f;   // all 512 slots
    __syncthreads();

    float pz[4];
    #pragma unroll
    for (int i = 0; i < 4; i++)
        pz[i] = zx[((size_t)(r0 + i)*Tt + 0)*G1 + j];

    for (int t = 0; t < Tt; t++) {
        float nz[4] = {0.f, 0.f, 0.f, 0.f};
        const bool pf = (t + 1 < Tt);
        if (pf) {
            #pragma unroll
            for (int i = 0; i < 4; i++)
                nz[i] = zx[((size_t)(r0 + i)*Tt + t + 1)*G1 + j];
        }
        ull a0 = pack2(pz[0], b1j);
        ull a1 = pack2(pz[1], b1j);
        ull a2 = pack2(pz[2], b1j);
        ull a3 = pack2(pz[3], b1j);

        const ulonglong2* hv2 = (const ulonglong2*)sV;
        #pragma unroll
        for (int i = 0; i < 16; i++) {
            ulonglong2 hA = hv2[i*2];
            ulonglong2 hB = hv2[i*2 + 1];
            ffma2(a0, rU[i], hA.x);
            ffma2(a1, rU[i], hA.y);
            ffma2(a2, rU[i], hB.x);
            ffma2(a3, rU[i], hB.y);
        }
        #pragma unroll 8
        for (int i = 0; i < 48; i++) {
            ull u2 = sUp[i*G1 + j];
            ulonglong2 hA = hv2[(16+i)*2];
            ulonglong2 hB = hv2[(16+i)*2 + 1];
            ffma2(a0, u2, hA.x);
            ffma2(a1, u2, hA.y);
            ffma2(a2, u2, hB.x);
            ffma2(a3, u2, hB.y);
        }
        float2 f0 = unpk2(a0), f1 = unpk2(a1), f2 = unpk2(a2), f3 = unpk2(a3);
        sZ4[j] = make_float4(f0.x + f0.y, f1.x + f1.y, f2.x + f2.y, f3.x + f3.y);
        __syncthreads();

        const float* zf = (const float*)sZ4;
        float zi = zf[(m      )*4 + rr];
        float zfv= zf[(m + 128)*4 + rr];
        float zg = zf[(m + 256)*4 + rr];
        float zo = zf[(m + 384)*4 + rr];
        float ig = sigf(zi), fg = sigf(zfv), og = sigf(zo);
        float gg = fmaxf(zg, 0.f);
        creg = fmaf(fg, creg, ig * gg);
        float h = og * fmaxf(creg, 0.f);
        sV[(m>>1)*8 + rr*2 + (m&1)] = h;
        g_h1[((size_t)(r0 + rr)*Tt + t)*H1C + m] = fmaf(h, bnsc, bnsh);
        #pragma unroll
        for (int i = 0; i < 4; i++) pz[i] = nz[i];
        __syncthreads();
    }
}

// ---------------------------------------------------------------------------
// Kernel: LSTM2 recurrence only (k=64) + BN2. 128 CTAs x 4 rows, 512 thr.
// ---------------------------------------------------------------------------
#define SMEM2_BYTES (512*16 + 256*4)

__global__ void __launch_bounds__(512, 1) lstm2_kernel(
    const float* __restrict__ u2, const float* __restrict__ b2,
    const float* __restrict__ g2, const float* __restrict__ be2,
    const float* __restrict__ m2, const float* __restrict__ v2)
{
    extern __shared__ char smraw[];
    float4* sZp = (float4*)smraw;            // [2][256]
    float*  sV  = (float*)(sZp + 512);       // [32 pairs][4][2] = 256 floats

    const int j    = threadIdx.x;
    const int jc   = j & 255;
    const int half = j >> 8;
    const int r0   = blockIdx.x * RWS;
    const float* zx = g_zx2;

    ull rW[16];
    #pragma unroll
    for (int p = 0; p < 16; p++)
        rW[p] = pack2(u2[(32*half + 2*p)*G2 + jc], u2[(32*half + 2*p + 1)*G2 + jc]);
    const float bj = b2[jc];

    const int rr = jc >> 6, m = j & 63;
    const float bnsc = g2[m] / sqrtf(v2[m] + 1e-3f);
    const float bnsh = be2[m] - bnsc * m2[m];
    float creg = 0.f;

    if (j < 256) sV[j] = 0.f;
    __syncthreads();

    float pz[4] = {0.f, 0.f, 0.f, 0.f};
    if (half == 0) {
        #pragma unroll
        for (int i = 0; i < 4; i++)
            pz[i] = zx[((size_t)(r0 + i)*Tt + 0)*G2 + jc];
    }

    for (int t = 0; t < Tt; t++) {
        float nz[4] = {0.f, 0.f, 0.f, 0.f};
        const bool pf = (t + 1 < Tt);
        if (pf && half == 0) {
            #pragma unroll
            for (int i = 0; i < 4; i++)
                nz[i] = zx[((size_t)(r0 + i)*Tt + t + 1)*G2 + jc];
        }
        ull a0, a1, a2, a3;
        if (half == 0) {
            a0 = pack2(pz[0], bj); a1 = pack2(pz[1], bj);
            a2 = pack2(pz[2], bj); a3 = pack2(pz[3], bj);
        } else {
            a0 = pack2(0.f, 0.f); a1 = a0; a2 = a0; a3 = a0;
        }
        const ulonglong2* hv2 = (const ulonglong2*)sV;
        const int gb = 16 * half;
        #pragma unroll
        for (int p = 0; p < 16; p++) {
            ulonglong2 hA = hv2[(gb + p)*2];
            ulonglong2 hB = hv2[(gb + p)*2 + 1];
            ffma2(a0, rW[p], hA.x);
            ffma2(a1, rW[p], hA.y);
            ffma2(a2, rW[p], hB.x);
            ffma2(a3, rW[p], hB.y);
        }
        float2 f0 = unpk2(a0), f1 = unpk2(a1), f2 = unpk2(a2), f3 = unpk2(a3);
        sZp[half*G2 + jc] = make_float4(f0.x + f0.y, f1.x + f1.y, f2.x + f2.y, f3.x + f3.y);
        __syncthreads();

        if (j < 256) {
            const float* zf = (const float*)sZp;
            float zi = zf[(m      )*4 + rr] + zf[(256 + m      )*4 + rr];
            float zfv= zf[(m +  64)*4 + rr] + zf[(256 + m +  64)*4 + rr];
            float zg = zf[(m + 128)*4 + rr] + zf[(256 + m + 128)*4 + rr];
            float zo = zf[(m + 192)*4 + rr] + zf[(256 + m + 192)*4 + rr];
            float ig = sigf(zi), fg = sigf(zfv), og = sigf(zo);
            float gg = fmaxf(zg, 0.f);
            creg = fmaf(fg, creg, ig * gg);
            float h = og * fmaxf(creg, 0.f);
            sV[(m>>1)*8 + rr*2 + (m&1)] = h;
            if (t == Tt - 1)
                g_h2[(r0 + rr)*H2C + m] = fmaf(h, bnsc, bnsh);
        }
        #pragma unroll
        for (int i = 0; i < 4; i++) pz[i] = nz[i];
        __syncthreads();
    }
}

// ---------------------------------------------------------------------------
// Kernel: logits + exp. 125 CTAs x 256 vocab columns.
// ---------------------------------------------------------------------------
#define H2T_STRIDE 514
#define SMEM3_BYTES (H2C * H2T_STRIDE * 4)

__global__ void __launch_bounds__(256, 1) head_kernel(
    const float* __restrict__ wd, const float* __restrict__ bd,
    float* __restrict__ out)
{
    extern __shared__ float sH2t[];
    const int j = threadIdx.x;
    const int v = blockIdx.x * 256 + j;

    for (int i = j; i < Bsz*H2C; i += 256) {
        int r = i >> 6, k = i & 63;
        sH2t[k*H2T_STRIDE + r] = g_h2[i];
    }
    ull rwd2[H2C];
    #pragma unroll
    for (int k = 0; k < H2C; k++) {
        float w = wd[(size_t)k*VV + v];
        rwd2[k] = pack2(w, w);
    }
    const float bdv = bd[v];
    const ull bb = pack2(bdv, bdv);
    __syncthreads();

    for (int r = 0; r < Bsz; r += 4) {
        ull a01 = bb, a23 = bb;
        #pragma unroll 16
        for (int k = 0; k < H2C; k++) {
            const float* hp = sH2t + k*H2T_STRIDE + r;
            ull h01 = *(const ull*)(hp);
            ull h23 = *(const ull*)(hp + 2);
            ffma2(a01, rwd2[k], h01);
            ffma2(a23, rwd2[k], h23);
        }
        float2 f01 = unpk2(a01), f23 = unpk2(a23);
        out[(size_t)(r + 0)*VV + v] = __expf(f01.x);
        out[(size_t)(r + 1)*VV + v] = __expf(f01.y);
        out[(size_t)(r + 2)*VV + v] = __expf(f23.x);
        out[(size_t)(r + 3)*VV + v] = __expf(f23.y);
    }
}

// ---------------------------------------------------------------------------
// Kernel: per-row normalize.
// ---------------------------------------------------------------------------
__global__ void __launch_bounds__(256, 1) softmax_norm_kernel(float* __restrict__ out)
{
    __shared__ float warp_s[8];
    __shared__ float inv_s;
    const int r = blockIdx.x;
    float4* p = (float4*)(out + (size_t)r * VV);

    float s = 0.f;
    for (int i = threadIdx.x; i < VV/4; i += 256) {
        float4 v = p[i];
        s += (v.x + v.y) + (v.z + v.w);
    }
    #pragma unroll
    for (int o = 16; o > 0; o >>= 1) s += __shfl_down_sync(0xffffffffu, s, o);
    if ((threadIdx.x & 31) == 0) warp_s[threadIdx.x >> 5] = s;
    __syncthreads();
    if (threadIdx.x == 0) {
        float tt = 0.f;
        #pragma unroll
        for (int i = 0; i < 8; i++) tt += warp_s[i];
        inv_s = 1.0f / tt;
    }
    __syncthreads();
    const float inv = inv_s;
    for (int i = threadIdx.x; i < VV/4; i += 256) {
        float4 v = p[i];
        v.x *= inv; v.y *= inv; v.z *= inv; v.w *= inv;
        p[i] = v;
    }
}

// ---------------------------------------------------------------------------
extern "C" void kernel_launch(void* const* d_in, const int* in_sizes, int n_in,
                              void* d_out, int out_size)
{
    const int*   ids = (const int*)  d_in[0];
    const float* emb = (const float*)d_in[1];
    const float* w1  = (const float*)d_in[2];
    const float* u1  = (const float*)d_in[3];
    const float* b1  = (const float*)d_in[4];
    const float* g1  = (const float*)d_in[5];
    const float* be1 = (const float*)d_in[6];
    const float* m1  = (const float*)d_in[7];
    const float* v1  = (const float*)d_in[8];
    const float* w2  = (const float*)d_in[9];
    const float* u2  = (const float*)d_in[10];
    const float* b2  = (const float*)d_in[11];
    const float* g2  = (const float*)d_in[12];
    const float* be2 = (const float*)d_in[13];
    const float* m2  = (const float*)d_in[14];
    const float* v2  = (const float*)d_in[15];
    const float* wd  = (const float*)d_in[16];
    const float* bd  = (const float*)d_in[17];
    float* out = (float*)d_out;

    cudaFuncSetAttribute(zx1_gemm,     cudaFuncAttributeMaxDynamicSharedMemorySize, ZX1_SMEM);
    cudaFuncSetAttribute(zx2_gemm,     cudaFuncAttributeMaxDynamicSharedMemorySize, ZX2_SMEM);
    cudaFuncSetAttribute(lstm1_kernel, cudaFuncAttributeMaxDynamicSharedMemorySize, SMEM1_BYTES);
    cudaFuncSetAttribute(lstm2_kernel, cudaFuncAttributeMaxDynamicSharedMemorySize, SMEM2_BYTES);
    cudaFuncSetAttribute(head_kernel,  cudaFuncAttributeMaxDynamicSharedMemorySize, SMEM3_BYTES);

    zx1_gemm<<<NR/128, 256, ZX1_SMEM>>>(ids, emb, w1);
    lstm1_kernel<<<Bsz/RWS, 512, SMEM1_BYTES>>>(u1, b1, g1, be1, m1, v1);
    zx2_gemm<<<dim3(NR/128, 2), 256, ZX2_SMEM>>>(w2);
    lstm2_kernel<<<Bsz/RWS, 512, SMEM2_BYTES>>>(u2, b2, g2, be2, m2, v2);
    head_kernel<<<VV/256, 256, SMEM3_BYTES>>>(wd, bd, out);
    softmax_norm_kernel<<<Bsz, 256>>>(out);
}